// round 15
// baseline (speedup 1.0000x reference)
#include <cuda_runtime.h>
#include <cuda_fp16.h>
#include <cstdint>
#include <cfloat>

// Problem constants
#define BB 8192
#define CC 64
#define KK 256
#define DD 64
#define N1 (BB*CC)            // 524288
#define NCENT (CC*KK*DD)      // 1048576
#define TTILES 4
#define NGX 16                // BB / (128*TTILES)

// Scaling: response computed as r' = (16 x)·(64 cent) = 1024 r.
// Argmax and BN output are invariant (we unscale before the +eps).
// Purpose: keep fp16 residual splits OUT of the subnormal range (<2^-14),
// which caused the R12 rel_err jump to 1.4e-4.
#define SX   16.0f
#define SC   64.0f
#define RS   1024.0           // SX*SC
#define INVRS (1.0f/1024.0f)

// -------- static device scratch (no allocations allowed) --------
__device__ __align__(16) __half g_ch[NCENT];   // h split of 64*cent, [c][k][d]
__device__ __align__(16) __half g_cl[NCENT];   // l split (residual)
__device__ int    g_codei[N1];     // [c][b]
__device__ float  g_selv[N1];      // [c][b] (scaled by RS)
__device__ float2 g_part[CC*NGX];  // scaled sums
__device__ float  g_mean[CC];      // unscaled
__device__ float  g_invstd[CC];    // unscaled

// ---------------- smem layout (dynamic) ----------------
#define SM_B      0u        // 2 splits x 32768  (256 rows x 128B, swizzled)
#define SM_A      65536u    // 2 bufs x 2 splits x 16384
#define A_BUF     32768u
#define A_SPLIT   16384u
#define SM_CAND   131072u   // 2 bufs x (128 rows x 2 warpN x float2)
#define CAND_BUF  2048u
#define SM_RED    135168u   // 8 x float2
#define SM_TOTAL  135232u

#define SWZ(o) ((uint32_t)(o) ^ ((((uint32_t)(o))>>3)&0x70u))

// per-warp-pair named barrier (64 threads; ids 1..4)
#define PBAR(p) asm volatile("bar.sync %0, 64;" :: "r"((p)+1) : "memory")

// ---------------- PTX helpers (portable sm_80+ only) ----------------
static __device__ __forceinline__ uint32_t smem_u32(const void* p){
    uint32_t a;
    asm("{ .reg .u64 t; cvta.to.shared.u64 t, %1; cvt.u32.u64 %0, t; }"
        : "=r"(a) : "l"(p));
    return a;
}
static __device__ __forceinline__ void ldsm4(uint32_t* r, uint32_t addr){
    asm volatile("ldmatrix.sync.aligned.m8n8.x4.shared.b16 {%0,%1,%2,%3}, [%4];"
        : "=r"(r[0]), "=r"(r[1]), "=r"(r[2]), "=r"(r[3]) : "r"(addr));
}
static __device__ __forceinline__ void mma16816(float* c, const uint32_t* a,
                                                uint32_t b0, uint32_t b1){
    asm volatile(
        "mma.sync.aligned.m16n8k16.row.col.f32.f16.f16.f32 "
        "{%0,%1,%2,%3}, {%4,%5,%6,%7}, {%8,%9}, {%0,%1,%2,%3};"
        : "+f"(c[0]), "+f"(c[1]), "+f"(c[2]), "+f"(c[3])
        : "r"(a[0]), "r"(a[1]), "r"(a[2]), "r"(a[3]), "r"(b0), "r"(b1));
}

// ---------------- conversion helpers ----------------
// fp16 2-way split of PRE-SCALED value: x = h + l + r2, |r2| <= 2^-22 |x|.
static __device__ __forceinline__ void split2(float x, __half& h, __half& l){
    h = __float2half_rn(x);
    l = __float2half_rn(x - __half2float(h));
}
static __device__ __forceinline__ uint32_t pk(__half a, __half b){
    __half2 t = __halves2half2(a, b);
    return *reinterpret_cast<uint32_t*>(&t);
}

// ---- pair-local x load: each 64-thread pair loads its own 32 A-rows ----
static __device__ __forceinline__ void loadX(float4* xr, const float* __restrict__ x,
                                             int gx, int c, int t,
                                             int pair, int pairTid){
    const int b0 = (gx*TTILES + t)*128;
    const int f4 = pairTid & 15;
    #pragma unroll
    for (int i = 0; i < 8; ++i){
        int row = pair*32 + i*4 + (pairTid >> 4);
        xr[i] = ((const float4*)x)[((size_t)(b0+row)*CC + c)*(DD/4) + f4];
    }
}
// ---- pair-local convert: registers -> 2 fp16 splits in smem (x scaled by SX) ----
static __device__ __forceinline__ void storeSplits(char* sm, uint32_t abase,
                                                   const float4* xr,
                                                   int pair, int pairTid){
    const int f4 = pairTid & 15;
    #pragma unroll
    for (int i = 0; i < 8; ++i){
        int row = pair*32 + i*4 + (pairTid >> 4);
        float f[4] = {xr[i].x*SX, xr[i].y*SX, xr[i].z*SX, xr[i].w*SX};
        __half h[4], l[4];
        #pragma unroll
        for (int p = 0; p < 4; ++p) split2(f[p], h[p], l[p]);
        uint32_t so = SWZ(row*128 + f4*8);
        *(uint2*)(sm + abase + so)           = make_uint2(pk(h[0],h[1]), pk(h[2],h[3]));
        *(uint2*)(sm + abase + A_SPLIT + so) = make_uint2(pk(l[0],l[1]), pk(l[2],l[3]));
    }
}

// ---------------------------------------------------------------------------
// Main kernel: grid (NGX, CC), 256 threads, warp grid 4(m) x 2(n),
// warp tile 32x64, N in two 128-halves. 4-pass fp16 2-split GEMM on mma.sync:
//   sb=1 (l'): {l*l', h*l'}   sb=0 (h'): {l*h', h*h'}   (small terms first)
// Each 64-thread warp-pair owns its 32 A rows end-to-end (pair-local barrier).
// ---------------------------------------------------------------------------
__global__ __launch_bounds__(256, 1)
void mma_kernel(const float* __restrict__ x, const float* __restrict__ gamma){
    extern __shared__ __align__(16) char sm[];
    const uint32_t smb = smem_u32(sm);
    const int tid = threadIdx.x, lane = tid & 31, wid = tid >> 5;
    const int warpM = wid >> 1, warpN = wid & 1, q = lane >> 2;
    const int pair = warpM, pairTid = tid & 63;
    const int gx = blockIdx.x, c = blockIdx.y;

    // ---- load 2 B splits into swizzled smem (64KB, whole block) ----
    {
        const uint4* cbh = (const uint4*)g_ch;
        const uint4* cbl = (const uint4*)g_cl;
        #pragma unroll
        for (int i = 0; i < 16; ++i){
            int flat = i*256 + tid;          // 0..4095
            int s    = flat >> 11;
            int g    = flat & 2047;
            int row  = g >> 3, q8 = g & 7;
            const uint4* src = s ? cbl : cbh;
            uint4 v = src[((size_t)c*KK + row)*8 + q8];
            *(uint4*)(sm + SM_B + (uint32_t)s*32768u + SWZ(row*128 + q8*16)) = v;
        }
    }

    const float gmm = gamma[c];
    const bool wantMin = (gmm < 0.f);
    float sum = 0.f, sum2 = 0.f;

    // per-lane ldmatrix address components
    const uint32_t aRow  = (uint32_t)(warpM*32 + (lane & 15));
    const uint32_t aCol  = (uint32_t)((lane >> 4) << 4);       // 0 or 16 bytes
    const uint32_t bRowL = (uint32_t)(((lane >> 4) << 3) + (lane & 7));
    const uint32_t bCol  = (uint32_t)((lane & 8) << 1);        // 0 or 16 bytes

    // 4-pass tables grouped by B split (low-magnitude first within each group)
    const int SBt[2] = {1, 0};           // B: l' group, then h' group
    const int SAt[2][2] = {{1,0},{1,0}}; // A within group: l, then h

    // prologue: load + convert tile 0 (pair-local rows); full sync covers B too
    float4 xr[8];
    loadX(xr, x, gx, c, 0, pair, pairTid);
    storeSplits(sm, SM_A, xr, pair, pairTid);
    __syncthreads();

    #pragma unroll 1
    for (int t = 0; t < TTILES; ++t){
        // prefetch next x tile into registers (hidden under compute)
        if (t+1 < TTILES) loadX(xr, x, gx, c, t+1, pair, pairTid);

        const uint32_t abase = SM_A + (uint32_t)(t&1)*A_BUF;
        float2* cand = (float2*)(sm + SM_CAND + (uint32_t)(t&1)*CAND_BUF);

        // single-extremum running candidates per owned row-slot
        float rE[4]; int rI[4];
        #pragma unroll
        for (int s4 = 0; s4 < 4; ++s4){
            rE[s4] = wantMin ? FLT_MAX : -FLT_MAX; rI[s4] = 0;
        }

        #pragma unroll
        for (int nh = 0; nh < 2; ++nh){
            float acc[2][8][4];
            #pragma unroll
            for (int mi = 0; mi < 2; ++mi)
                #pragma unroll
                for (int nj = 0; nj < 8; ++nj)
                    #pragma unroll
                    for (int e = 0; e < 4; ++e) acc[mi][nj][e] = 0.f;

            #pragma unroll
            for (int ks = 0; ks < 4; ++ks){
                uint32_t aF[2][2][4];
                #pragma unroll
                for (int s = 0; s < 2; ++s)
                    #pragma unroll
                    for (int mi = 0; mi < 2; ++mi)
                        ldsm4(aF[s][mi], smb + abase + (uint32_t)s*A_SPLIT +
                              SWZ(aRow*128u + (uint32_t)mi*2048u +
                                  (uint32_t)ks*32u + aCol));
                #pragma unroll
                for (int g3 = 0; g3 < 2; ++g3){
                    const int sb = SBt[g3];
                    uint32_t bF[4][4];
                    #pragma unroll
                    for (int njp = 0; njp < 4; ++njp)
                        ldsm4(bF[njp], smb + SM_B + (uint32_t)sb*32768u +
                              SWZ((uint32_t)(nh*128 + warpN*64 + njp*16 + bRowL)*128u +
                                  (uint32_t)ks*32u + bCol));
                    #pragma unroll
                    for (int pi = 0; pi < 2; ++pi){
                        const int sa = SAt[g3][pi];
                        #pragma unroll
                        for (int mi = 0; mi < 2; ++mi)
                            #pragma unroll
                            for (int njp = 0; njp < 4; ++njp){
                                mma16816(acc[mi][2*njp],   aF[sa][mi], bF[njp][0], bF[njp][1]);
                                mma16816(acc[mi][2*njp+1], aF[sa][mi], bF[njp][2], bF[njp][3]);
                            }
                    }
                }
            }

            // ---- epilogue scan (uniform branch: track only needed extremum) ----
            const int kbase = nh*128 + warpN*64 + 2*(lane & 3);
            if (!wantMin){
                #pragma unroll
                for (int mi = 0; mi < 2; ++mi)
                    #pragma unroll
                    for (int nj = 0; nj < 8; ++nj){
                        const int k0 = kbase + nj*8;
                        float v0 = acc[mi][nj][0], v1 = acc[mi][nj][1];
                        float v2 = acc[mi][nj][2], v3 = acc[mi][nj][3];
                        sum += v0 + v1 + v2 + v3;
                        sum2 = fmaf(v0, v0, sum2); sum2 = fmaf(v1, v1, sum2);
                        sum2 = fmaf(v2, v2, sum2); sum2 = fmaf(v3, v3, sum2);
                        const int s0 = mi*2, s1 = mi*2 + 1;
                        if (v0 > rE[s0]){ rE[s0] = v0; rI[s0] = k0;   }
                        if (v1 > rE[s0]){ rE[s0] = v1; rI[s0] = k0+1; }
                        if (v2 > rE[s1]){ rE[s1] = v2; rI[s1] = k0;   }
                        if (v3 > rE[s1]){ rE[s1] = v3; rI[s1] = k0+1; }
                    }
            } else {
                #pragma unroll
                for (int mi = 0; mi < 2; ++mi)
                    #pragma unroll
                    for (int nj = 0; nj < 8; ++nj){
                        const int k0 = kbase + nj*8;
                        float v0 = acc[mi][nj][0], v1 = acc[mi][nj][1];
                        float v2 = acc[mi][nj][2], v3 = acc[mi][nj][3];
                        sum += v0 + v1 + v2 + v3;
                        sum2 = fmaf(v0, v0, sum2); sum2 = fmaf(v1, v1, sum2);
                        sum2 = fmaf(v2, v2, sum2); sum2 = fmaf(v3, v3, sum2);
                        const int s0 = mi*2, s1 = mi*2 + 1;
                        if (v0 < rE[s0]){ rE[s0] = v0; rI[s0] = k0;   }
                        if (v1 < rE[s0]){ rE[s0] = v1; rI[s0] = k0+1; }
                        if (v2 < rE[s1]){ rE[s1] = v2; rI[s1] = k0;   }
                        if (v3 < rE[s1]){ rE[s1] = v3; rI[s1] = k0+1; }
                    }
            }
        }

        // ---- cross-lane (quad) reduce, write candidates (pair-local rows) ----
        #pragma unroll
        for (int s4 = 0; s4 < 4; ++s4){
            float ev = rE[s4]; int ei = rI[s4];
            #pragma unroll
            for (int off = 1; off <= 2; off <<= 1){
                float ov = __shfl_xor_sync(0xffffffffu, ev, off);
                int   oi = __shfl_xor_sync(0xffffffffu, ei, off);
                bool take = wantMin ? (ov < ev || (ov == ev && oi < ei))
                                    : (ov > ev || (ov == ev && oi < ei));
                if (take){ ev = ov; ei = oi; }
            }
            if ((lane & 3) == 0){
                int row = warpM*32 + (s4 >> 1)*16 + (s4 & 1)*8 + q;
                cand[row*2 + warpN] = make_float2(ev, __int_as_float(ei));
            }
        }

        // convert next tile into the other A buffer (pair-local rows)
        if (t+1 < TTILES)
            storeSplits(sm, SM_A + (uint32_t)((t+1)&1)*A_BUF, xr, pair, pairTid);

        PBAR(pair);   // pair-local: covers cand(t) AND this pair's A(t+1)

        // ---- merge across the two n-warps, write staged outputs ----
        if (pairTid < 32){
            const int r_ = pair*32 + pairTid;
            float2 c0 = cand[r_*2 + 0], c1 = cand[r_*2 + 1];
            float ev = c0.x; int ei = __float_as_int(c0.y);
            int   oi = __float_as_int(c1.y);
            bool take = wantMin ? (c1.x < ev || (c1.x == ev && oi < ei))
                                : (c1.x > ev || (c1.x == ev && oi < ei));
            if (take){ ev = c1.x; ei = oi; }
            const int b = (gx*TTILES + t)*128 + r_;
            int code; float sv;
            if (gmm != 0.f){ code = ei; sv = ev;  }
            else           { code = 0;  sv = 0.f; }
            g_codei[(size_t)c*BB + b] = code;
            g_selv [(size_t)c*BB + b] = sv;
        }
    }

    // ---- per-block stats partial (deterministic; scaled domain) ----
    #pragma unroll
    for (int off = 16; off; off >>= 1){
        sum  += __shfl_xor_sync(0xffffffffu, sum,  off);
        sum2 += __shfl_xor_sync(0xffffffffu, sum2, off);
    }
    float2* red = (float2*)(sm + SM_RED);
    if (lane == 0) red[wid] = make_float2(sum, sum2);
    __syncthreads();
    if (tid == 0){
        float s = 0.f, s2 = 0.f;
        #pragma unroll
        for (int w = 0; w < 8; ++w){ s += red[w].x; s2 += red[w].y; }
        g_part[c*NGX + gx] = make_float2(s, s2);
    }
}

// ---------------------------------------------------------------------------
// Prep: centroid (scaled by SC) fp16 2-way splits + passthrough to out
// ---------------------------------------------------------------------------
__global__ void prep_kernel(const float4* __restrict__ cent,
                            float4* __restrict__ outc){
    int i = blockIdx.x*256 + threadIdx.x;    // < NCENT/4
    float4 v = cent[i];
    outc[i] = v;
    float f[4] = {v.x*SC, v.y*SC, v.z*SC, v.w*SC};
    __half h[4], l[4];
    #pragma unroll
    for (int p = 0; p < 4; ++p) split2(f[p], h[p], l[p]);
    ((uint2*)g_ch)[i] = make_uint2(pk(h[0],h[1]), pk(h[2],h[3]));
    ((uint2*)g_cl)[i] = make_uint2(pk(l[0],l[1]), pk(l[2],l[3]));
}

// ---------------------------------------------------------------------------
// Stats reduce: 16 partials per channel -> mean, invstd (UNSCALED domain,
// so the +BN_EPS matches the reference bit-for-bit in semantics)
// ---------------------------------------------------------------------------
__global__ void pass2_kernel(){
    int c = threadIdx.x;
    if (c < CC){
        double s = 0.0, s2 = 0.0;
        for (int i = 0; i < NGX; ++i){
            float2 p = g_part[c*NGX + i];
            s += (double)p.x; s2 += (double)p.y;
        }
        const double cnt = (double)BB*(double)KK;
        double mean = (s / RS) / cnt;
        double var  = (s2 / (RS*RS)) / cnt - mean*mean;
        g_mean[c]   = (float)mean;
        g_invstd[c] = rsqrtf((float)var + 1e-5f);
    }
}

// ---------------------------------------------------------------------------
// Finalize: unscale selected value, normalize, transpose, write out
// ---------------------------------------------------------------------------
__global__ __launch_bounds__(256)
void pass3_kernel(const float* __restrict__ gamma, const float* __restrict__ beta,
                  float* __restrict__ out){
    __shared__ float tc[16][65];
    __shared__ float tv[16][65];
    const int tid = threadIdx.x;
    const int b0  = blockIdx.x*16;
    #pragma unroll
    for (int i = 0; i < 4; ++i){
        int flat = i*256 + tid;           // 0..1023
        int cc = flat >> 4, bq = flat & 15;
        int b  = b0 + bq;
        float g = gamma[cc];
        int  code = g_codei[(size_t)cc*BB + b];
        float val;
        if (g != 0.f)
            val = (g_selv[(size_t)cc*BB + b]*INVRS - g_mean[cc])*g_invstd[cc]*g
                  + beta[cc];
        else
            val = beta[cc];
        tc[bq][cc] = (float)code;
        tv[bq][cc] = val;
    }
    __syncthreads();
    #pragma unroll
    for (int i = 0; i < 4; ++i){
        int flat = i*256 + tid;
        int row = flat >> 6, cc = flat & 63;
        size_t o = (size_t)(b0 + row)*CC + cc;
        out[o]      = tc[row][cc];
        out[N1 + o] = tv[row][cc];
    }
}

// ---------------------------------------------------------------------------
extern "C" void kernel_launch(void* const* d_in, const int* in_sizes, int n_in,
                              void* d_out, int out_size){
    (void)in_sizes; (void)n_in; (void)out_size;
    const float* x     = (const float*)d_in[0];
    const float* cent  = (const float*)d_in[1];
    const float* gamma = (const float*)d_in[2];
    const float* beta  = (const float*)d_in[3];
    float* out = (float*)d_out;

    cudaFuncSetAttribute(mma_kernel,
                         cudaFuncAttributeMaxDynamicSharedMemorySize, SM_TOTAL);

    prep_kernel<<<NCENT/4/256, 256>>>((const float4*)cent,
                                      (float4*)(out + 2*(size_t)N1));
    mma_kernel<<<dim3(NGX, CC), 256, SM_TOTAL>>>(x, gamma);
    pass2_kernel<<<1, 64>>>();
    pass3_kernel<<<BB/16, 256>>>(gamma, beta, out);
}

// round 17
// speedup vs baseline: 1.0840x; 1.0840x over previous
#include <cuda_runtime.h>
#include <cuda_fp16.h>
#include <cstdint>
#include <cfloat>

// Problem constants
#define BB 8192
#define CC 64
#define KK 256
#define DD 64
#define N1 (BB*CC)            // 524288
#define NCENT (CC*KK*DD)      // 1048576
#define TTILES 4
#define NGX 16                // BB / (128*TTILES)

// Scaling: response computed as r' = (16 x)·(64 cent) = 1024 r (kept from R15;
// harmless and exact). Flips stem from the scale-invariant r2 split residual —
// deterministic, rel_err 1.402267e-4 (7x under threshold). NUMERICS FROZEN.
#define SX   16.0f
#define SC   64.0f
#define RS   1024.0           // SX*SC
#define INVRS (1.0f/1024.0f)

// -------- static device scratch (no allocations allowed) --------
__device__ __align__(16) __half g_ch[NCENT];   // h split of 64*cent, [c][k][d]
__device__ __align__(16) __half g_cl[NCENT];   // l split (residual)
__device__ int    g_codei[N1];     // [c][b]
__device__ float  g_selv[N1];      // [c][b] (scaled by RS)
__device__ float2 g_part[CC*NGX];  // scaled sums
__device__ float  g_mean[CC];      // unscaled
__device__ float  g_invstd[CC];    // unscaled

// ---------------- smem layout (dynamic) ----------------
// Single-buffered A (pair-local hazard handled by the per-tile PBARs) to fit
// TWO blocks per SM: 100.5KB x 2 = 201KB <= 228KB.
#define SM_B      0u        // 2 splits x 32768  (256 rows x 128B, swizzled)
#define SM_A      65536u    // 1 buf x 2 splits x 16384
#define A_SPLIT   16384u
#define SM_CAND   98304u    // 2 bufs x (128 rows x 2 warpN x float2)
#define CAND_BUF  2048u
#define SM_RED    102400u   // 8 x float2
#define SM_TOTAL  102464u

#define SWZ(o) ((uint32_t)(o) ^ ((((uint32_t)(o))>>3)&0x70u))

// per-warp-pair named barrier (64 threads; ids 1..4)
#define PBAR(p) asm volatile("bar.sync %0, 64;" :: "r"((p)+1) : "memory")

// ---------------- PTX helpers (portable sm_80+ only) ----------------
static __device__ __forceinline__ uint32_t smem_u32(const void* p){
    uint32_t a;
    asm("{ .reg .u64 t; cvta.to.shared.u64 t, %1; cvt.u32.u64 %0, t; }"
        : "=r"(a) : "l"(p));
    return a;
}
static __device__ __forceinline__ void ldsm4(uint32_t* r, uint32_t addr){
    asm volatile("ldmatrix.sync.aligned.m8n8.x4.shared.b16 {%0,%1,%2,%3}, [%4];"
        : "=r"(r[0]), "=r"(r[1]), "=r"(r[2]), "=r"(r[3]) : "r"(addr));
}
static __device__ __forceinline__ void mma16816(float* c, const uint32_t* a,
                                                uint32_t b0, uint32_t b1){
    asm volatile(
        "mma.sync.aligned.m16n8k16.row.col.f32.f16.f16.f32 "
        "{%0,%1,%2,%3}, {%4,%5,%6,%7}, {%8,%9}, {%0,%1,%2,%3};"
        : "+f"(c[0]), "+f"(c[1]), "+f"(c[2]), "+f"(c[3])
        : "r"(a[0]), "r"(a[1]), "r"(a[2]), "r"(a[3]), "r"(b0), "r"(b1));
}

// ---------------- conversion helpers ----------------
// fp16 2-way split of PRE-SCALED value: x = h + l + r2, |r2| <= 2^-22 |x|.
static __device__ __forceinline__ void split2(float x, __half& h, __half& l){
    h = __float2half_rn(x);
    l = __float2half_rn(x - __half2float(h));
}
static __device__ __forceinline__ uint32_t pk(__half a, __half b){
    __half2 t = __halves2half2(a, b);
    return *reinterpret_cast<uint32_t*>(&t);
}

// ---- pair-local x load: each 64-thread pair loads its own 32 A-rows ----
static __device__ __forceinline__ void loadX(float4* xr, const float* __restrict__ x,
                                             int gx, int c, int t,
                                             int pair, int pairTid){
    const int b0 = (gx*TTILES + t)*128;
    const int f4 = pairTid & 15;
    #pragma unroll
    for (int i = 0; i < 8; ++i){
        int row = pair*32 + i*4 + (pairTid >> 4);
        xr[i] = ((const float4*)x)[((size_t)(b0+row)*CC + c)*(DD/4) + f4];
    }
}
// ---- pair-local convert: registers -> 2 fp16 splits in smem (x scaled by SX) ----
static __device__ __forceinline__ void storeSplits(char* sm, const float4* xr,
                                                   int pair, int pairTid){
    const int f4 = pairTid & 15;
    #pragma unroll
    for (int i = 0; i < 8; ++i){
        int row = pair*32 + i*4 + (pairTid >> 4);
        float f[4] = {xr[i].x*SX, xr[i].y*SX, xr[i].z*SX, xr[i].w*SX};
        __half h[4], l[4];
        #pragma unroll
        for (int p = 0; p < 4; ++p) split2(f[p], h[p], l[p]);
        uint32_t so = SWZ(row*128 + f4*8);
        *(uint2*)(sm + SM_A + so)           = make_uint2(pk(h[0],h[1]), pk(h[2],h[3]));
        *(uint2*)(sm + SM_A + A_SPLIT + so) = make_uint2(pk(l[0],l[1]), pk(l[2],l[3]));
    }
}

// ---------------------------------------------------------------------------
// Main kernel: grid (NGX, CC), 256 threads, warp grid 4(m) x 2(n),
// warp tile 32x64, N in two 128-halves. 4-pass fp16 2-split GEMM on mma.sync:
//   sb=1 (l'): {l*l', h*l'}   sb=0 (h'): {l*h', h*h'}   (small terms first)
// Each 64-thread warp-pair owns its 32 A rows end-to-end. A single-buffered;
// per-tile: convert -> PBAR -> MMA+scan -> PBAR -> merge. Two blocks per SM
// cover each other's load/convert/barrier gaps (the ~13% exposed non-MMA time
// measured at 1 block/SM).
// ---------------------------------------------------------------------------
__global__ __launch_bounds__(256, 2)
void mma_kernel(const float* __restrict__ x, const float* __restrict__ gamma){
    extern __shared__ __align__(16) char sm[];
    const uint32_t smb = smem_u32(sm);
    const int tid = threadIdx.x, lane = tid & 31, wid = tid >> 5;
    const int warpM = wid >> 1, warpN = wid & 1, q = lane >> 2;
    const int pair = warpM, pairTid = tid & 63;
    const int gx = blockIdx.x, c = blockIdx.y;

    // ---- load 2 B splits into swizzled smem (64KB, whole block) ----
    {
        const uint4* cbh = (const uint4*)g_ch;
        const uint4* cbl = (const uint4*)g_cl;
        #pragma unroll
        for (int i = 0; i < 16; ++i){
            int flat = i*256 + tid;          // 0..4095
            int s    = flat >> 11;
            int g    = flat & 2047;
            int row  = g >> 3, q8 = g & 7;
            const uint4* src = s ? cbl : cbh;
            uint4 v = src[((size_t)c*KK + row)*8 + q8];
            *(uint4*)(sm + SM_B + (uint32_t)s*32768u + SWZ(row*128 + q8*16)) = v;
        }
    }
    __syncthreads();   // B visible to all warps (A handled per-pair below)

    const float gmm = gamma[c];
    const bool wantMin = (gmm < 0.f);
    float sum = 0.f, sum2 = 0.f;

    // per-lane ldmatrix address components
    const uint32_t aRow  = (uint32_t)(warpM*32 + (lane & 15));
    const uint32_t aCol  = (uint32_t)((lane >> 4) << 4);       // 0 or 16 bytes
    const uint32_t bRowL = (uint32_t)(((lane >> 4) << 3) + (lane & 7));
    const uint32_t bCol  = (uint32_t)((lane & 8) << 1);        // 0 or 16 bytes

    // 4-pass tables grouped by B split (low-magnitude first within each group)
    const int SBt[2] = {1, 0};           // B: l' group, then h' group
    const int SAt[2][2] = {{1,0},{1,0}}; // A within group: l, then h

    #pragma unroll 1
    for (int t = 0; t < TTILES; ++t){
        // inline load + convert this tile (pair-local rows); latency covered
        // by the co-resident block
        {
            float4 xr[8];
            loadX(xr, x, gx, c, t, pair, pairTid);
            storeSplits(sm, xr, pair, pairTid);
        }
        PBAR(pair);    // A(t) ready for this pair

        float2* cand = (float2*)(sm + SM_CAND + (uint32_t)(t&1)*CAND_BUF);

        // single-extremum running candidates per owned row-slot
        float rE[4]; int rI[4];
        #pragma unroll
        for (int s4 = 0; s4 < 4; ++s4){
            rE[s4] = wantMin ? FLT_MAX : -FLT_MAX; rI[s4] = 0;
        }

        #pragma unroll
        for (int nh = 0; nh < 2; ++nh){
            float acc[2][8][4];
            #pragma unroll
            for (int mi = 0; mi < 2; ++mi)
                #pragma unroll
                for (int nj = 0; nj < 8; ++nj)
                    #pragma unroll
                    for (int e = 0; e < 4; ++e) acc[mi][nj][e] = 0.f;

            #pragma unroll
            for (int ks = 0; ks < 4; ++ks){
                uint32_t aF[2][2][4];
                #pragma unroll
                for (int s = 0; s < 2; ++s)
                    #pragma unroll
                    for (int mi = 0; mi < 2; ++mi)
                        ldsm4(aF[s][mi], smb + SM_A + (uint32_t)s*A_SPLIT +
                              SWZ(aRow*128u + (uint32_t)mi*2048u +
                                  (uint32_t)ks*32u + aCol));
                #pragma unroll
                for (int g3 = 0; g3 < 2; ++g3){
                    const int sb = SBt[g3];
                    uint32_t bF[4][4];
                    #pragma unroll
                    for (int njp = 0; njp < 4; ++njp)
                        ldsm4(bF[njp], smb + SM_B + (uint32_t)sb*32768u +
                              SWZ((uint32_t)(nh*128 + warpN*64 + njp*16 + bRowL)*128u +
                                  (uint32_t)ks*32u + bCol));
                    #pragma unroll
                    for (int pi = 0; pi < 2; ++pi){
                        const int sa = SAt[g3][pi];
                        #pragma unroll
                        for (int mi = 0; mi < 2; ++mi)
                            #pragma unroll
                            for (int njp = 0; njp < 4; ++njp){
                                mma16816(acc[mi][2*njp],   aF[sa][mi], bF[njp][0], bF[njp][1]);
                                mma16816(acc[mi][2*njp+1], aF[sa][mi], bF[njp][2], bF[njp][3]);
                            }
                    }
                }
            }

            // ---- epilogue scan (uniform branch: track only needed extremum) ----
            const int kbase = nh*128 + warpN*64 + 2*(lane & 3);
            if (!wantMin){
                #pragma unroll
                for (int mi = 0; mi < 2; ++mi)
                    #pragma unroll
                    for (int nj = 0; nj < 8; ++nj){
                        const int k0 = kbase + nj*8;
                        float v0 = acc[mi][nj][0], v1 = acc[mi][nj][1];
                        float v2 = acc[mi][nj][2], v3 = acc[mi][nj][3];
                        sum += v0 + v1 + v2 + v3;
                        sum2 = fmaf(v0, v0, sum2); sum2 = fmaf(v1, v1, sum2);
                        sum2 = fmaf(v2, v2, sum2); sum2 = fmaf(v3, v3, sum2);
                        const int s0 = mi*2, s1 = mi*2 + 1;
                        if (v0 > rE[s0]){ rE[s0] = v0; rI[s0] = k0;   }
                        if (v1 > rE[s0]){ rE[s0] = v1; rI[s0] = k0+1; }
                        if (v2 > rE[s1]){ rE[s1] = v2; rI[s1] = k0;   }
                        if (v3 > rE[s1]){ rE[s1] = v3; rI[s1] = k0+1; }
                    }
            } else {
                #pragma unroll
                for (int mi = 0; mi < 2; ++mi)
                    #pragma unroll
                    for (int nj = 0; nj < 8; ++nj){
                        const int k0 = kbase + nj*8;
                        float v0 = acc[mi][nj][0], v1 = acc[mi][nj][1];
                        float v2 = acc[mi][nj][2], v3 = acc[mi][nj][3];
                        sum += v0 + v1 + v2 + v3;
                        sum2 = fmaf(v0, v0, sum2); sum2 = fmaf(v1, v1, sum2);
                        sum2 = fmaf(v2, v2, sum2); sum2 = fmaf(v3, v3, sum2);
                        const int s0 = mi*2, s1 = mi*2 + 1;
                        if (v0 < rE[s0]){ rE[s0] = v0; rI[s0] = k0;   }
                        if (v1 < rE[s0]){ rE[s0] = v1; rI[s0] = k0+1; }
                        if (v2 < rE[s1]){ rE[s1] = v2; rI[s1] = k0;   }
                        if (v3 < rE[s1]){ rE[s1] = v3; rI[s1] = k0+1; }
                    }
            }
        }

        // ---- cross-lane (quad) reduce, write candidates (pair-local rows) ----
        #pragma unroll
        for (int s4 = 0; s4 < 4; ++s4){
            float ev = rE[s4]; int ei = rI[s4];
            #pragma unroll
            for (int off = 1; off <= 2; off <<= 1){
                float ov = __shfl_xor_sync(0xffffffffu, ev, off);
                int   oi = __shfl_xor_sync(0xffffffffu, ei, off);
                bool take = wantMin ? (ov < ev || (ov == ev && oi < ei))
                                    : (ov > ev || (ov == ev && oi < ei));
                if (take){ ev = ov; ei = oi; }
            }
            if ((lane & 3) == 0){
                int row = warpM*32 + (s4 >> 1)*16 + (s4 & 1)*8 + q;
                cand[row*2 + warpN] = make_float2(ev, __int_as_float(ei));
            }
        }

        PBAR(pair);   // cand(t) ready; both pair warps done reading A(t)

        // ---- merge across the two n-warps, write staged outputs ----
        if (pairTid < 32){
            const int r_ = pair*32 + pairTid;
            float2 c0 = cand[r_*2 + 0], c1 = cand[r_*2 + 1];
            float ev = c0.x; int ei = __float_as_int(c0.y);
            int   oi = __float_as_int(c1.y);
            bool take = wantMin ? (c1.x < ev || (c1.x == ev && oi < ei))
                                : (c1.x > ev || (c1.x == ev && oi < ei));
            if (take){ ev = c1.x; ei = oi; }
            const int b = (gx*TTILES + t)*128 + r_;
            int code; float sv;
            if (gmm != 0.f){ code = ei; sv = ev;  }
            else           { code = 0;  sv = 0.f; }
            g_codei[(size_t)c*BB + b] = code;
            g_selv [(size_t)c*BB + b] = sv;
        }
    }

    // ---- per-block stats partial (deterministic; scaled domain) ----
    #pragma unroll
    for (int off = 16; off; off >>= 1){
        sum  += __shfl_xor_sync(0xffffffffu, sum,  off);
        sum2 += __shfl_xor_sync(0xffffffffu, sum2, off);
    }
    float2* red = (float2*)(sm + SM_RED);
    if (lane == 0) red[wid] = make_float2(sum, sum2);
    __syncthreads();
    if (tid == 0){
        float s = 0.f, s2 = 0.f;
        #pragma unroll
        for (int w = 0; w < 8; ++w){ s += red[w].x; s2 += red[w].y; }
        g_part[c*NGX + gx] = make_float2(s, s2);
    }
}

// ---------------------------------------------------------------------------
// Prep: centroid (scaled by SC) fp16 2-way splits + passthrough to out
// ---------------------------------------------------------------------------
__global__ void prep_kernel(const float4* __restrict__ cent,
                            float4* __restrict__ outc){
    int i = blockIdx.x*256 + threadIdx.x;    // < NCENT/4
    float4 v = cent[i];
    outc[i] = v;
    float f[4] = {v.x*SC, v.y*SC, v.z*SC, v.w*SC};
    __half h[4], l[4];
    #pragma unroll
    for (int p = 0; p < 4; ++p) split2(f[p], h[p], l[p]);
    ((uint2*)g_ch)[i] = make_uint2(pk(h[0],h[1]), pk(h[2],h[3]));
    ((uint2*)g_cl)[i] = make_uint2(pk(l[0],l[1]), pk(l[2],l[3]));
}

// ---------------------------------------------------------------------------
// Stats reduce: 16 partials per channel -> mean, invstd (UNSCALED domain,
// so the +BN_EPS matches the reference bit-for-bit in semantics)
// ---------------------------------------------------------------------------
__global__ void pass2_kernel(){
    int c = threadIdx.x;
    if (c < CC){
        double s = 0.0, s2 = 0.0;
        for (int i = 0; i < NGX; ++i){
            float2 p = g_part[c*NGX + i];
            s += (double)p.x; s2 += (double)p.y;
        }
        const double cnt = (double)BB*(double)KK;
        double mean = (s / RS) / cnt;
        double var  = (s2 / (RS*RS)) / cnt - mean*mean;
        g_mean[c]   = (float)mean;
        g_invstd[c] = rsqrtf((float)var + 1e-5f);
    }
}

// ---------------------------------------------------------------------------
// Finalize: unscale selected value, normalize, transpose, write out
// ---------------------------------------------------------------------------
__global__ __launch_bounds__(256)
void pass3_kernel(const float* __restrict__ gamma, const float* __restrict__ beta,
                  float* __restrict__ out){
    __shared__ float tc[16][65];
    __shared__ float tv[16][65];
    const int tid = threadIdx.x;
    const int b0  = blockIdx.x*16;
    #pragma unroll
    for (int i = 0; i < 4; ++i){
        int flat = i*256 + tid;           // 0..1023
        int cc = flat >> 4, bq = flat & 15;
        int b  = b0 + bq;
        float g = gamma[cc];
        int  code = g_codei[(size_t)cc*BB + b];
        float val;
        if (g != 0.f)
            val = (g_selv[(size_t)cc*BB + b]*INVRS - g_mean[cc])*g_invstd[cc]*g
                  + beta[cc];
        else
            val = beta[cc];
        tc[bq][cc] = (float)code;
        tv[bq][cc] = val;
    }
    __syncthreads();
    #pragma unroll
    for (int i = 0; i < 4; ++i){
        int flat = i*256 + tid;
        int row = flat >> 6, cc = flat & 63;
        size_t o = (size_t)(b0 + row)*CC + cc;
        out[o]      = tc[row][cc];
        out[N1 + o] = tv[row][cc];
    }
}

// ---------------------------------------------------------------------------
extern "C" void kernel_launch(void* const* d_in, const int* in_sizes, int n_in,
                              void* d_out, int out_size){
    (void)in_sizes; (void)n_in; (void)out_size;
    const float* x     = (const float*)d_in[0];
    const float* cent  = (const float*)d_in[1];
    const float* gamma = (const float*)d_in[2];
    const float* beta  = (const float*)d_in[3];
    float* out = (float*)d_out;

    cudaFuncSetAttribute(mma_kernel,
                         cudaFuncAttributeMaxDynamicSharedMemorySize, SM_TOTAL);

    prep_kernel<<<NCENT/4/256, 256>>>((const float4*)cent,
                                      (float4*)(out + 2*(size_t)N1));
    mma_kernel<<<dim3(NGX, CC), 256, SM_TOTAL>>>(x, gamma);
    pass2_kernel<<<1, 64>>>();
    pass3_kernel<<<BB/16, 256>>>(gamma, beta, out);
}